// round 9
// baseline (speedup 1.0000x reference)
#include <cuda_runtime.h>
#include <cuda_bf16.h>
#include <cstdint>

#define N_NODES 20000
#define D_IN 512
#define D_OUT 64
#define N_EDGES 160000

// ---------------------------------------------------------------------------
// device globals (no allocation allowed)
// ---------------------------------------------------------------------------
__device__ float g_buf0[(size_t)N_NODES * D_IN];   // h1 / h3
__device__ float g_buf1[(size_t)N_NODES * D_IN];   // h2
__device__ int g_deg[N_NODES];
__device__ int g_off[N_NODES + 1];
__device__ int g_cursor[N_NODES];
__device__ int g_adj[N_EDGES];
__device__ __nv_bfloat16 g_w1_hi[D_IN * D_IN];
__device__ __nv_bfloat16 g_w1_lo[D_IN * D_IN];
__device__ __nv_bfloat16 g_w2_hi[D_OUT * D_IN];
__device__ __nv_bfloat16 g_w2_lo[D_OUT * D_IN];
__device__ __nv_bfloat16 g_a_hi[(size_t)N_NODES * D_IN];
__device__ __nv_bfloat16 g_a_lo[(size_t)N_NODES * D_IN];

// ---------------------------------------------------------------------------
// CSR build
// ---------------------------------------------------------------------------
__global__ void csr_zero_deg(int* deg) {
    int i = blockIdx.x * blockDim.x + threadIdx.x;
    if (i < N_NODES) deg[i] = 0;
}
__global__ void csr_hist(const int* __restrict__ dst, int* __restrict__ deg) {
    int e = blockIdx.x * blockDim.x + threadIdx.x;
    if (e < N_EDGES) atomicAdd(&deg[dst[e]], 1);
}
__global__ void csr_scan(const int* __restrict__ deg, int* __restrict__ off,
                         int* __restrict__ cursor) {
    __shared__ int ssum[1024];
    const int t = threadIdx.x;
    const int ITEMS = 20;
    int base = t * ITEMS;
    int local[ITEMS];
    int s = 0;
#pragma unroll
    for (int i = 0; i < ITEMS; i++) {
        int idx = base + i;
        int v = (idx < N_NODES) ? deg[idx] : 0;
        local[i] = s;
        s += v;
    }
    ssum[t] = s;
    __syncthreads();
    for (int d = 1; d < 1024; d <<= 1) {
        int v = (t >= d) ? ssum[t - d] : 0;
        __syncthreads();
        ssum[t] += v;
        __syncthreads();
    }
    int prev = (t > 0) ? ssum[t - 1] : 0;
#pragma unroll
    for (int i = 0; i < ITEMS; i++) {
        int idx = base + i;
        if (idx < N_NODES) {
            int o = prev + local[i];
            off[idx] = o;
            cursor[idx] = o;
        }
    }
    if (t == 1023) off[N_NODES] = ssum[1023];
}
__global__ void csr_fill(const int* __restrict__ src, const int* __restrict__ dst,
                         int* __restrict__ cursor, int* __restrict__ adj) {
    int e = blockIdx.x * blockDim.x + threadIdx.x;
    if (e < N_EDGES) {
        int p = atomicAdd(&cursor[dst[e]], 1);
        adj[p] = src[e];
    }
}

// ---------------------------------------------------------------------------
// Gather propagate (one block of 128 per node, float4 per thread)
// ---------------------------------------------------------------------------
__global__ void gather_prop(const float* __restrict__ x,
                            const int* __restrict__ off,
                            const int* __restrict__ adj,
                            float* __restrict__ out) {
    const int node = blockIdx.x;
    const int t = threadIdx.x;
    int b = off[node];
    int e = off[node + 1];
    float4 acc = make_float4(0.f, 0.f, 0.f, 0.f);
    int i = b;
    for (; i + 1 < e; i += 2) {
        int s0 = adj[i];
        int s1 = adj[i + 1];
        float4 v0 = reinterpret_cast<const float4*>(x + (size_t)s0 * D_IN)[t];
        float4 v1 = reinterpret_cast<const float4*>(x + (size_t)s1 * D_IN)[t];
        acc.x += v0.x + v1.x;
        acc.y += v0.y + v1.y;
        acc.z += v0.z + v1.z;
        acc.w += v0.w + v1.w;
    }
    if (i < e) {
        int s0 = adj[i];
        float4 v0 = reinterpret_cast<const float4*>(x + (size_t)s0 * D_IN)[t];
        acc.x += v0.x;
        acc.y += v0.y;
        acc.z += v0.z;
        acc.w += v0.w;
    }
    reinterpret_cast<float4*>(out + (size_t)node * D_IN)[t] = acc;
}

// ---------------------------------------------------------------------------
// Split fp32 -> bf16 hi/lo (scalar for weights, float4 for activations)
// ---------------------------------------------------------------------------
__global__ void split_w(const float* __restrict__ w, __nv_bfloat16* __restrict__ hi,
                        __nv_bfloat16* __restrict__ lo, int n) {
    int i = blockIdx.x * blockDim.x + threadIdx.x;
    if (i < n) {
        float a = w[i];
        __nv_bfloat16 h = __float2bfloat16_rn(a);
        hi[i] = h;
        lo[i] = __float2bfloat16_rn(a - __bfloat162float(h));
    }
}

__global__ void split4(const float4* __restrict__ w, uint2* __restrict__ hi,
                       uint2* __restrict__ lo, int n4) {
    int i = blockIdx.x * blockDim.x + threadIdx.x;
    if (i >= n4) return;
    float4 v = w[i];
    __nv_bfloat16 h0 = __float2bfloat16_rn(v.x);
    __nv_bfloat16 h1 = __float2bfloat16_rn(v.y);
    __nv_bfloat16 h2 = __float2bfloat16_rn(v.z);
    __nv_bfloat16 h3 = __float2bfloat16_rn(v.w);
    union { __nv_bfloat162 b[2]; uint2 u; } H, L;
    H.b[0] = __halves2bfloat162(h0, h1);
    H.b[1] = __halves2bfloat162(h2, h3);
    L.b[0] = __halves2bfloat162(
        __float2bfloat16_rn(v.x - __bfloat162float(h0)),
        __float2bfloat16_rn(v.y - __bfloat162float(h1)));
    L.b[1] = __halves2bfloat162(
        __float2bfloat16_rn(v.z - __bfloat162float(h2)),
        __float2bfloat16_rn(v.w - __bfloat162float(h3)));
    hi[i] = H.u;
    lo[i] = L.u;
}

// ---------------------------------------------------------------------------
// mma.sync helpers
// ---------------------------------------------------------------------------
__device__ __forceinline__ void mma_bf16(float* d, const uint32_t* a,
                                         const uint32_t* b) {
    asm volatile(
        "mma.sync.aligned.m16n8k16.row.col.f32.bf16.bf16.f32 "
        "{%0,%1,%2,%3}, {%4,%5,%6,%7}, {%8,%9}, {%0,%1,%2,%3};"
        : "+f"(d[0]), "+f"(d[1]), "+f"(d[2]), "+f"(d[3])
        : "r"(a[0]), "r"(a[1]), "r"(a[2]), "r"(a[3]), "r"(b[0]), "r"(b[1]));
}

__device__ __forceinline__ void ldmx4(uint32_t* r, uint32_t addr) {
    asm volatile(
        "ldmatrix.sync.aligned.m8n8.x4.shared.b16 {%0,%1,%2,%3}, [%4];"
        : "=r"(r[0]), "=r"(r[1]), "=r"(r[2]), "=r"(r[3])
        : "r"(addr));
}

#define CP16(dst, src, sz) \
    asm volatile("cp.async.ca.shared.global [%0], [%1], 16, %2;" \
                 :: "r"(dst), "l"(src), "r"(sz))
#define CP_COMMIT() asm volatile("cp.async.commit_group;")
#define CP_WAIT(n)  asm volatile("cp.async.wait_group %0;" :: "n"(n))

// ---------------------------------------------------------------------------
// GEMM1 (pre-split A): C = relu(A[M,512] @ B[N,512]^T)
// A/B bf16 hi+lo in global. CTA tile 128x64, BK=32, cp.async 2-stage pipeline.
// 8 warps, each a 32x32 tile (3-term split-bf16 mma).
// ---------------------------------------------------------------------------
#define PS_STRIDE 80
#define PS_AH 0
#define PS_AL 10240
#define PS_BH 20480
#define PS_BL 25600
#define PS_STAGE 30720
#define PS_SMEM (2 * PS_STAGE)   // 61440

template <bool RELU>
__global__ __launch_bounds__(256)
void gemm_ps(const __nv_bfloat16* __restrict__ Ah,
             const __nv_bfloat16* __restrict__ Al,
             const __nv_bfloat16* __restrict__ Bh,
             const __nv_bfloat16* __restrict__ Bl,
             float* __restrict__ C, int M, int N) {
    extern __shared__ __align__(16) char smem[];
    const int tid = threadIdx.x;
    const int lane = tid & 31;
    const int wid = tid >> 5;
    const int wm = wid & 3;
    const int wn = wid >> 2;
    const int m0 = blockIdx.x * 128;
    const int n0 = blockIdx.y * 64;
    const uint32_t sb = (uint32_t)__cvta_generic_to_shared(smem);

    float acc[2][4][4];
#pragma unroll
    for (int i = 0; i < 2; i++)
#pragma unroll
        for (int j = 0; j < 4; j++)
#pragma unroll
            for (int k = 0; k < 4; k++) acc[i][j][k] = 0.f;

    // load mapping: A row=tid/2, two 16B chunks; B row=tid/4, one 16B chunk
    const int ar = tid >> 1;
    const int ac = (tid & 1) * 2;
    const int am = m0 + ar;
    const uint32_t a_sz = (am < M) ? 16u : 0u;
    const int am_c = (am < M) ? am : 0;
    const int br = tid >> 2;
    const int bc = tid & 3;

    const uint32_t a_dst = sb + PS_AH + (uint32_t)(ar * PS_STRIDE + ac * 16);
    const uint32_t al_dst = sb + PS_AL + (uint32_t)(ar * PS_STRIDE + ac * 16);
    const uint32_t bh_dst = sb + PS_BH + (uint32_t)(br * PS_STRIDE + bc * 16);
    const uint32_t bl_dst = sb + PS_BL + (uint32_t)(br * PS_STRIDE + bc * 16);

#define PS_ISSUE(kc, stg) do {                                                  \
    uint32_t so_ = (stg) * PS_STAGE;                                            \
    const __nv_bfloat16* gah_ = Ah + (size_t)am_c * D_IN + (kc) * 32 + ac * 8;  \
    const __nv_bfloat16* gal_ = Al + (size_t)am_c * D_IN + (kc) * 32 + ac * 8;  \
    CP16(a_dst + so_, gah_, a_sz);                                              \
    CP16(a_dst + so_ + 16, gah_ + 8, a_sz);                                     \
    CP16(al_dst + so_, gal_, a_sz);                                             \
    CP16(al_dst + so_ + 16, gal_ + 8, a_sz);                                    \
    const __nv_bfloat16* gbh_ = Bh + (size_t)(n0 + br) * D_IN + (kc) * 32 + bc * 8; \
    const __nv_bfloat16* gbl_ = Bl + (size_t)(n0 + br) * D_IN + (kc) * 32 + bc * 8; \
    CP16(bh_dst + so_, gbh_, 16u);                                              \
    CP16(bl_dst + so_, gbl_, 16u);                                              \
    CP_COMMIT();                                                                \
} while (0)

    const uint32_t a_lm = sb + (uint32_t)((wm * 32 + (lane & 15)) * PS_STRIDE +
                                          (lane >> 4) * 16);
    const uint32_t b_lm = sb + PS_BH + (uint32_t)((wn * 32 + (lane & 15)) * PS_STRIDE +
                                                  (lane >> 4) * 16);

    PS_ISSUE(0, 0);

    for (int kc = 0; kc < 16; kc++) {
        const int cur = kc & 1;
        if (kc + 1 < 16) {
            PS_ISSUE(kc + 1, cur ^ 1);
            CP_WAIT(1);
        } else {
            CP_WAIT(0);
        }
        __syncthreads();

        const uint32_t so = cur * PS_STAGE;
#pragma unroll
        for (int ks = 0; ks < 2; ks++) {
            uint32_t aH[2][4], aL[2][4], bH[2][4], bL[2][4];
#pragma unroll
            for (int mi = 0; mi < 2; mi++) {
                uint32_t addr = a_lm + so + mi * 16 * PS_STRIDE + ks * 32;
                ldmx4(aH[mi], addr);
                ldmx4(aL[mi], addr + PS_AL);
            }
#pragma unroll
            for (int ng = 0; ng < 2; ng++) {
                uint32_t addr = b_lm + so + ng * 16 * PS_STRIDE + ks * 32;
                ldmx4(bH[ng], addr);
                ldmx4(bL[ng], addr + (PS_BL - PS_BH));
            }
#pragma unroll
            for (int mi = 0; mi < 2; mi++) {
#pragma unroll
                for (int ng = 0; ng < 2; ng++) {
#pragma unroll
                    for (int nb = 0; nb < 2; nb++) {
                        int ni = ng * 2 + nb;
                        uint32_t bh2[2] = {bH[ng][nb], bH[ng][nb + 2]};
                        uint32_t bl2[2] = {bL[ng][nb], bL[ng][nb + 2]};
                        mma_bf16(acc[mi][ni], aH[mi], bh2);
                        mma_bf16(acc[mi][ni], aH[mi], bl2);
                        mma_bf16(acc[mi][ni], aL[mi], bh2);
                    }
                }
            }
        }
        __syncthreads();
    }

    // epilogue
    const int g = lane >> 2;
    const int t4 = lane & 3;
#pragma unroll
    for (int mi = 0; mi < 2; mi++) {
#pragma unroll
        for (int ni = 0; ni < 4; ni++) {
            int col = n0 + wn * 32 + ni * 8 + t4 * 2;
            int row0 = m0 + wm * 32 + mi * 16 + g;
            int row1 = row0 + 8;
            float2 v0 = make_float2(acc[mi][ni][0], acc[mi][ni][1]);
            float2 v1 = make_float2(acc[mi][ni][2], acc[mi][ni][3]);
            if (RELU) {
                v0.x = fmaxf(v0.x, 0.f); v0.y = fmaxf(v0.y, 0.f);
                v1.x = fmaxf(v1.x, 0.f); v1.y = fmaxf(v1.y, 0.f);
            }
            if (row0 < M)
                *reinterpret_cast<float2*>(C + (size_t)row0 * N + col) = v0;
            if (row1 < M)
                *reinterpret_cast<float2*>(C + (size_t)row1 * N + col) = v1;
        }
    }
}

// ---------------------------------------------------------------------------
// GEMM2 (fp32 A, inline convert): used once, N=64
// ---------------------------------------------------------------------------
#define LDS_STRIDE 80
#define SM_AH 0
#define SM_AL (128 * LDS_STRIDE)
#define SM_BH (2 * 128 * LDS_STRIDE)
#define SM_BL (2 * 128 * LDS_STRIDE + 64 * LDS_STRIDE)
#define SM_TOTAL (2 * 128 * LDS_STRIDE + 2 * 64 * LDS_STRIDE)

template <bool RELU>
__global__ __launch_bounds__(256)
void gemm_mma(const float* __restrict__ A,
              const __nv_bfloat16* __restrict__ Bh,
              const __nv_bfloat16* __restrict__ Bl,
              float* __restrict__ C, int M, int N) {
    __shared__ __align__(16) char smem[SM_TOTAL];
    const int tid = threadIdx.x;
    const int lane = tid & 31;
    const int wid = tid >> 5;
    const int wm = wid & 3;
    const int wn = wid >> 2;
    const int m0 = blockIdx.x * 128;
    const int n0 = blockIdx.y * 64;

    const uint32_t sb = (uint32_t)__cvta_generic_to_shared(smem);

    float acc[2][4][4];
#pragma unroll
    for (int i = 0; i < 2; i++)
#pragma unroll
        for (int j = 0; j < 4; j++)
#pragma unroll
            for (int k = 0; k < 4; k++) acc[i][j][k] = 0.f;

    const int ar = tid >> 1;
    const int ah = tid & 1;
    const bool arow_ok = (m0 + ar) < M;
    const int br = tid >> 2;
    const int bq = tid & 3;

    const uint32_t a_lm = sb + (uint32_t)((wm * 32 + (lane & 15)) * LDS_STRIDE +
                                          (lane >> 4) * 16);
    const uint32_t b_lm = sb + SM_BH + (uint32_t)((wn * 32 + (lane & 15)) * LDS_STRIDE +
                                                  (lane >> 4) * 16);

    for (int kc = 0; kc < 16; kc++) {
        float4 av[4];
        if (arow_ok) {
            const float4* ap = reinterpret_cast<const float4*>(
                A + (size_t)(m0 + ar) * D_IN + kc * 32 + ah * 16);
#pragma unroll
            for (int i = 0; i < 4; i++) av[i] = ap[i];
        } else {
#pragma unroll
            for (int i = 0; i < 4; i++) av[i] = make_float4(0.f, 0.f, 0.f, 0.f);
        }
        const uint4 bhv = *reinterpret_cast<const uint4*>(
            Bh + (size_t)(n0 + br) * D_IN + kc * 32 + bq * 8);
        const uint4 blv = *reinterpret_cast<const uint4*>(
            Bl + (size_t)(n0 + br) * D_IN + kc * 32 + bq * 8);

        __syncthreads();

        {
            union { __nv_bfloat162 h2[8]; uint4 u[2]; } hi, lo;
            const float* f = reinterpret_cast<const float*>(av);
#pragma unroll
            for (int j = 0; j < 8; j++) {
                float a0 = f[2 * j], a1 = f[2 * j + 1];
                __nv_bfloat16 h0 = __float2bfloat16_rn(a0);
                __nv_bfloat16 h1 = __float2bfloat16_rn(a1);
                hi.h2[j] = __halves2bfloat162(h0, h1);
                lo.h2[j] = __halves2bfloat162(
                    __float2bfloat16_rn(a0 - __bfloat162float(h0)),
                    __float2bfloat16_rn(a1 - __bfloat162float(h1)));
            }
            char* pa = smem + ar * LDS_STRIDE + ah * 32;
            *reinterpret_cast<uint4*>(pa + SM_AH) = hi.u[0];
            *reinterpret_cast<uint4*>(pa + SM_AH + 16) = hi.u[1];
            *reinterpret_cast<uint4*>(pa + SM_AL) = lo.u[0];
            *reinterpret_cast<uint4*>(pa + SM_AL + 16) = lo.u[1];
        }
        {
            char* pb = smem + br * LDS_STRIDE + bq * 16;
            *reinterpret_cast<uint4*>(pb + SM_BH) = bhv;
            *reinterpret_cast<uint4*>(pb + SM_BL) = blv;
        }
        __syncthreads();

#pragma unroll
        for (int ks = 0; ks < 2; ks++) {
            uint32_t aH[2][4], aL[2][4], bH[2][4], bL[2][4];
#pragma unroll
            for (int mi = 0; mi < 2; mi++) {
                uint32_t addr = a_lm + mi * 16 * LDS_STRIDE + ks * 32;
                ldmx4(aH[mi], addr);
                ldmx4(aL[mi], addr + (SM_AL - SM_AH));
            }
#pragma unroll
            for (int ng = 0; ng < 2; ng++) {
                uint32_t addr = b_lm + ng * 16 * LDS_STRIDE + ks * 32;
                ldmx4(bH[ng], addr);
                ldmx4(bL[ng], addr + (SM_BL - SM_BH));
            }
#pragma unroll
            for (int mi = 0; mi < 2; mi++) {
#pragma unroll
                for (int ng = 0; ng < 2; ng++) {
#pragma unroll
                    for (int nb = 0; nb < 2; nb++) {
                        int ni = ng * 2 + nb;
                        uint32_t bh2[2] = {bH[ng][nb], bH[ng][nb + 2]};
                        uint32_t bl2[2] = {bL[ng][nb], bL[ng][nb + 2]};
                        mma_bf16(acc[mi][ni], aH[mi], bh2);
                        mma_bf16(acc[mi][ni], aH[mi], bl2);
                        mma_bf16(acc[mi][ni], aL[mi], bh2);
                    }
                }
            }
        }
    }

    const int g = lane >> 2;
    const int t4 = lane & 3;
#pragma unroll
    for (int mi = 0; mi < 2; mi++) {
#pragma unroll
        for (int ni = 0; ni < 4; ni++) {
            int col = n0 + wn * 32 + ni * 8 + t4 * 2;
            int row0 = m0 + wm * 32 + mi * 16 + g;
            int row1 = row0 + 8;
            float2 v0 = make_float2(acc[mi][ni][0], acc[mi][ni][1]);
            float2 v1 = make_float2(acc[mi][ni][2], acc[mi][ni][3]);
            if (RELU) {
                v0.x = fmaxf(v0.x, 0.f); v0.y = fmaxf(v0.y, 0.f);
                v1.x = fmaxf(v1.x, 0.f); v1.y = fmaxf(v1.y, 0.f);
            }
            if (row0 < M)
                *reinterpret_cast<float2*>(C + (size_t)row0 * N + col) = v0;
            if (row1 < M)
                *reinterpret_cast<float2*>(C + (size_t)row1 * N + col) = v1;
        }
    }
}

// ---------------------------------------------------------------------------
// log_softmax in-place over rows of 64, one warp per row (2 elems/lane)
// ---------------------------------------------------------------------------
__global__ void log_softmax_kernel(float* __restrict__ out, int M) {
    int row = blockIdx.x * (blockDim.x >> 5) + (threadIdx.x >> 5);
    int lane = threadIdx.x & 31;
    if (row >= M) return;
    float* p = out + (size_t)row * D_OUT;
    float a = p[lane];
    float b = p[lane + 32];
    float mx = fmaxf(a, b);
#pragma unroll
    for (int off = 16; off > 0; off >>= 1)
        mx = fmaxf(mx, __shfl_xor_sync(0xffffffffu, mx, off));
    float s = expf(a - mx) + expf(b - mx);
#pragma unroll
    for (int off = 16; off > 0; off >>= 1)
        s += __shfl_xor_sync(0xffffffffu, s, off);
    float l = mx + logf(s);
    p[lane] = a - l;
    p[lane + 32] = b - l;
}

// ---------------------------------------------------------------------------
// launch
// ---------------------------------------------------------------------------
extern "C" void kernel_launch(void* const* d_in, const int* in_sizes, int n_in,
                              void* d_out, int out_size) {
    const float* x = (const float*)d_in[0];
    const int* ei = (const int*)d_in[1];
    const float* W1 = (const float*)d_in[2];
    const float* W2 = (const float*)d_in[3];
    float* out = (float*)d_out;

    const int* src = ei;
    const int* dst = ei + N_EDGES;

    float *h1, *h2;
    int *deg, *off, *cursor, *adj;
    __nv_bfloat16 *w1h, *w1l, *w2h, *w2l, *ahg, *alg;
    cudaGetSymbolAddress((void**)&h1, g_buf0);
    cudaGetSymbolAddress((void**)&h2, g_buf1);
    cudaGetSymbolAddress((void**)&deg, g_deg);
    cudaGetSymbolAddress((void**)&off, g_off);
    cudaGetSymbolAddress((void**)&cursor, g_cursor);
    cudaGetSymbolAddress((void**)&adj, g_adj);
    cudaGetSymbolAddress((void**)&w1h, g_w1_hi);
    cudaGetSymbolAddress((void**)&w1l, g_w1_lo);
    cudaGetSymbolAddress((void**)&w2h, g_w2_hi);
    cudaGetSymbolAddress((void**)&w2l, g_w2_lo);
    cudaGetSymbolAddress((void**)&ahg, g_a_hi);
    cudaGetSymbolAddress((void**)&alg, g_a_lo);

    cudaFuncSetAttribute(gemm_ps<true>,
                         cudaFuncAttributeMaxDynamicSharedMemorySize, PS_SMEM);

    // weight split
    split_w<<<(D_IN * D_IN + 255) / 256, 256>>>(W1, w1h, w1l, D_IN * D_IN);
    split_w<<<(D_OUT * D_IN + 255) / 256, 256>>>(W2, w2h, w2l, D_OUT * D_IN);

    // CSR build (by destination)
    csr_zero_deg<<<(N_NODES + 255) / 256, 256>>>(deg);
    csr_hist<<<(N_EDGES + 255) / 256, 256>>>(dst, deg);
    csr_scan<<<1, 1024>>>(deg, off, cursor);
    csr_fill<<<(N_EDGES + 255) / 256, 256>>>(src, dst, cursor, adj);

    const int n_mtiles = (N_NODES + 127) / 128;  // 157
    const int n4 = N_NODES * D_IN / 4;           // 2,560,000

    // propagate 1: h1 = segment_sum(x[src] -> dst)
    gather_prop<<<N_NODES, 128>>>(x, off, adj, h1);

    // split h1 -> bf16 hi/lo
    split4<<<(n4 + 255) / 256, 256>>>((const float4*)h1, (uint2*)ahg, (uint2*)alg, n4);

    // GEMM1 + ReLU: h2 = relu(h1 @ W1^T)
    {
        dim3 grid(n_mtiles, D_IN / 64);
        gemm_ps<true><<<grid, 256, PS_SMEM>>>(ahg, alg, w1h, w1l, h2, N_NODES, D_IN);
    }

    // propagate 2: h3(=h1) = segment_sum(h2[src] -> dst)
    gather_prop<<<N_NODES, 128>>>(h2, off, adj, h1);

    // GEMM2: out = h3 @ W2^T
    {
        dim3 grid(n_mtiles, 1);
        gemm_mma<false><<<grid, 256>>>(h1, w2h, w2l, out, N_NODES, D_OUT);
    }

    // log_softmax in-place
    log_softmax_kernel<<<(N_NODES + 7) / 8, 256>>>(out, N_NODES);
}

// round 10
// speedup vs baseline: 1.4398x; 1.4398x over previous
#include <cuda_runtime.h>
#include <cuda_bf16.h>
#include <cstdint>

#define N_NODES 20000
#define D_IN 512
#define D_OUT 64
#define N_EDGES 160000

// ---------------------------------------------------------------------------
// device globals (no allocation allowed)
// ---------------------------------------------------------------------------
__device__ float g_buf0[(size_t)N_NODES * D_IN];   // h1 / h3
__device__ float g_buf1[(size_t)N_NODES * D_IN];   // h2
__device__ int g_deg[N_NODES];
__device__ int g_off[N_NODES + 1];
__device__ int g_cursor[N_NODES];
__device__ int g_adj[N_EDGES];
__device__ __nv_bfloat16 g_w1_hi[D_IN * D_IN];
__device__ __nv_bfloat16 g_w1_lo[D_IN * D_IN];
__device__ __nv_bfloat16 g_w2_hi[D_OUT * D_IN];
__device__ __nv_bfloat16 g_w2_lo[D_OUT * D_IN];

// ---------------------------------------------------------------------------
// CSR build
// ---------------------------------------------------------------------------
__global__ void csr_zero_deg(int* deg) {
    int i = blockIdx.x * blockDim.x + threadIdx.x;
    if (i < N_NODES) deg[i] = 0;
}
__global__ void csr_hist(const int* __restrict__ dst, int* __restrict__ deg) {
    int e = blockIdx.x * blockDim.x + threadIdx.x;
    if (e < N_EDGES) atomicAdd(&deg[dst[e]], 1);
}
__global__ void csr_scan(const int* __restrict__ deg, int* __restrict__ off,
                         int* __restrict__ cursor) {
    __shared__ int ssum[1024];
    const int t = threadIdx.x;
    const int ITEMS = 20;
    int base = t * ITEMS;
    int local[ITEMS];
    int s = 0;
#pragma unroll
    for (int i = 0; i < ITEMS; i++) {
        int idx = base + i;
        int v = (idx < N_NODES) ? deg[idx] : 0;
        local[i] = s;
        s += v;
    }
    ssum[t] = s;
    __syncthreads();
    for (int d = 1; d < 1024; d <<= 1) {
        int v = (t >= d) ? ssum[t - d] : 0;
        __syncthreads();
        ssum[t] += v;
        __syncthreads();
    }
    int prev = (t > 0) ? ssum[t - 1] : 0;
#pragma unroll
    for (int i = 0; i < ITEMS; i++) {
        int idx = base + i;
        if (idx < N_NODES) {
            int o = prev + local[i];
            off[idx] = o;
            cursor[idx] = o;
        }
    }
    if (t == 1023) off[N_NODES] = ssum[1023];
}
__global__ void csr_fill(const int* __restrict__ src, const int* __restrict__ dst,
                         int* __restrict__ cursor, int* __restrict__ adj) {
    int e = blockIdx.x * blockDim.x + threadIdx.x;
    if (e < N_EDGES) {
        int p = atomicAdd(&cursor[dst[e]], 1);
        adj[p] = src[e];
    }
}

// ---------------------------------------------------------------------------
// Gather propagate (one block of 128 per node, float4 per thread)
// ---------------------------------------------------------------------------
__global__ void gather_prop(const float* __restrict__ x,
                            const int* __restrict__ off,
                            const int* __restrict__ adj,
                            float* __restrict__ out) {
    const int node = blockIdx.x;
    const int t = threadIdx.x;
    int b = off[node];
    int e = off[node + 1];
    float4 acc = make_float4(0.f, 0.f, 0.f, 0.f);
    int i = b;
    for (; i + 1 < e; i += 2) {
        int s0 = adj[i];
        int s1 = adj[i + 1];
        float4 v0 = reinterpret_cast<const float4*>(x + (size_t)s0 * D_IN)[t];
        float4 v1 = reinterpret_cast<const float4*>(x + (size_t)s1 * D_IN)[t];
        acc.x += v0.x + v1.x;
        acc.y += v0.y + v1.y;
        acc.z += v0.z + v1.z;
        acc.w += v0.w + v1.w;
    }
    if (i < e) {
        int s0 = adj[i];
        float4 v0 = reinterpret_cast<const float4*>(x + (size_t)s0 * D_IN)[t];
        acc.x += v0.x;
        acc.y += v0.y;
        acc.z += v0.z;
        acc.w += v0.w;
    }
    reinterpret_cast<float4*>(out + (size_t)node * D_IN)[t] = acc;
}

// ---------------------------------------------------------------------------
// Split fp32 weight matrix into bf16 hi/lo
// ---------------------------------------------------------------------------
__global__ void split_w(const float* __restrict__ w, __nv_bfloat16* __restrict__ hi,
                        __nv_bfloat16* __restrict__ lo, int n) {
    int i = blockIdx.x * blockDim.x + threadIdx.x;
    if (i < n) {
        float a = w[i];
        __nv_bfloat16 h = __float2bfloat16_rn(a);
        hi[i] = h;
        lo[i] = __float2bfloat16_rn(a - __bfloat162float(h));
    }
}

// ---------------------------------------------------------------------------
// mma.sync helpers
// ---------------------------------------------------------------------------
__device__ __forceinline__ void mma_bf16(float* d, const uint32_t* a,
                                         const uint32_t* b) {
    asm volatile(
        "mma.sync.aligned.m16n8k16.row.col.f32.bf16.bf16.f32 "
        "{%0,%1,%2,%3}, {%4,%5,%6,%7}, {%8,%9}, {%0,%1,%2,%3};"
        : "+f"(d[0]), "+f"(d[1]), "+f"(d[2]), "+f"(d[3])
        : "r"(a[0]), "r"(a[1]), "r"(a[2]), "r"(a[3]), "r"(b[0]), "r"(b[1]));
}

__device__ __forceinline__ void ldmx4(uint32_t* r, uint32_t addr) {
    asm volatile(
        "ldmatrix.sync.aligned.m8n8.x4.shared.b16 {%0,%1,%2,%3}, [%4];"
        : "=r"(r[0]), "=r"(r[1]), "=r"(r[2]), "=r"(r[3])
        : "r"(addr));
}

// ---------------------------------------------------------------------------
// Split-bf16 GEMM via mma.sync: C[M,N] = A[M,512] * B[N,512]^T
// A fp32 converted to hi/lo bf16 inline; B pre-split bf16 hi/lo.
// CTA tile 128 x BN (BN=128 or 64), BK=32, 8 warps each 32 x (BN/2).
// Register-prefetch pipeline: LDG(kc+1) issues before MMA(kc).
// smem rows padded to 80B -> conflict-free ldmatrix.
// ---------------------------------------------------------------------------
#define LDS_STRIDE 80

template <int BN, bool RELU>
__global__ __launch_bounds__(256)
void gemm_mma(const float* __restrict__ A,
              const __nv_bfloat16* __restrict__ Bh,
              const __nv_bfloat16* __restrict__ Bl,
              float* __restrict__ C, int M, int N) {
    constexpr int NI = BN / 16;          // n-blocks of 8 per warp
    constexpr int NG = BN / 32;          // ldmatrix groups per warp
    constexpr int SM_AH = 0;
    constexpr int SM_AL = 128 * LDS_STRIDE;
    constexpr int SM_BH = 2 * 128 * LDS_STRIDE;
    constexpr int SM_BL = SM_BH + BN * LDS_STRIDE;
    constexpr int SM_TOTAL = SM_BL + BN * LDS_STRIDE;
    constexpr int BPR = 256 / BN;        // threads per B row
    constexpr int BVEC = 4 / BPR;        // uint4 loads per thread per B tile

    __shared__ __align__(16) char smem[SM_TOTAL];
    const int tid = threadIdx.x;
    const int lane = tid & 31;
    const int wid = tid >> 5;
    const int wm = wid & 3;
    const int wn = wid >> 2;
    const int m0 = blockIdx.x * 128;
    const int n0 = blockIdx.y * BN;

    const uint32_t sb = (uint32_t)__cvta_generic_to_shared(smem);

    float acc[2][NI][4];
#pragma unroll
    for (int i = 0; i < 2; i++)
#pragma unroll
        for (int j = 0; j < NI; j++)
#pragma unroll
            for (int k = 0; k < 4; k++) acc[i][j][k] = 0.f;

    // A load mapping: row = tid/2, half = tid%2 (16 floats each)
    const int ar = tid >> 1;
    const int ah = tid & 1;
    const bool arow_ok = (m0 + ar) < M;
    // B load mapping: row = tid/BPR, chunk = tid%BPR (BVEC uint4 each)
    const int br = tid / BPR;
    const int bq = tid % BPR;

    const uint32_t a_lm = sb + (uint32_t)((wm * 32 + (lane & 15)) * LDS_STRIDE +
                                          (lane >> 4) * 16);
    const uint32_t b_lm = sb + SM_BH +
        (uint32_t)((wn * (BN / 2) + (lane & 15)) * LDS_STRIDE + (lane >> 4) * 16);

    float4 av[4];
    uint4 bhv[BVEC], blv[BVEC];

    // ---- prologue: prefetch tile 0 into registers ----
    auto load_tile = [&](int kc) {
        if (arow_ok) {
            const float4* ap = reinterpret_cast<const float4*>(
                A + (size_t)(m0 + ar) * D_IN + kc * 32 + ah * 16);
#pragma unroll
            for (int i = 0; i < 4; i++) av[i] = ap[i];
        } else {
#pragma unroll
            for (int i = 0; i < 4; i++) av[i] = make_float4(0.f, 0.f, 0.f, 0.f);
        }
        const uint4* bh = reinterpret_cast<const uint4*>(
            Bh + (size_t)(n0 + br) * D_IN + kc * 32 + bq * (8 * BVEC));
        const uint4* bl = reinterpret_cast<const uint4*>(
            Bl + (size_t)(n0 + br) * D_IN + kc * 32 + bq * (8 * BVEC));
#pragma unroll
        for (int i = 0; i < BVEC; i++) {
            bhv[i] = bh[i];
            blv[i] = bl[i];
        }
    };

    load_tile(0);

    for (int kc = 0; kc < 16; kc++) {
        __syncthreads();   // previous iter's ldmatrix reads done

        // ---- STS current tile (convert A fp32 -> bf16 hi/lo) ----
        {
            union { __nv_bfloat162 h2[8]; uint4 u[2]; } hi, lo;
            const float* f = reinterpret_cast<const float*>(av);
#pragma unroll
            for (int j = 0; j < 8; j++) {
                float a0 = f[2 * j], a1 = f[2 * j + 1];
                __nv_bfloat16 h0 = __float2bfloat16_rn(a0);
                __nv_bfloat16 h1 = __float2bfloat16_rn(a1);
                hi.h2[j] = __halves2bfloat162(h0, h1);
                lo.h2[j] = __halves2bfloat162(
                    __float2bfloat16_rn(a0 - __bfloat162float(h0)),
                    __float2bfloat16_rn(a1 - __bfloat162float(h1)));
            }
            char* pa = smem + ar * LDS_STRIDE + ah * 32;
            *reinterpret_cast<uint4*>(pa + SM_AH) = hi.u[0];
            *reinterpret_cast<uint4*>(pa + SM_AH + 16) = hi.u[1];
            *reinterpret_cast<uint4*>(pa + SM_AL) = lo.u[0];
            *reinterpret_cast<uint4*>(pa + SM_AL + 16) = lo.u[1];
        }
        {
            char* pb = smem + br * LDS_STRIDE + bq * (16 * BVEC);
#pragma unroll
            for (int i = 0; i < BVEC; i++) {
                *reinterpret_cast<uint4*>(pb + SM_BH + i * 16) = bhv[i];
                *reinterpret_cast<uint4*>(pb + SM_BL + i * 16) = blv[i];
            }
        }
        __syncthreads();

        // ---- prefetch next tile (hidden behind MMAs below) ----
        if (kc + 1 < 16) load_tile(kc + 1);

        // ---- compute: 2 ksteps of 16 ----
#pragma unroll
        for (int ks = 0; ks < 2; ks++) {
            uint32_t aH[2][4], aL[2][4], bH[NG][4], bL[NG][4];
#pragma unroll
            for (int mi = 0; mi < 2; mi++) {
                uint32_t addr = a_lm + mi * 16 * LDS_STRIDE + ks * 32;
                ldmx4(aH[mi], addr);
                ldmx4(aL[mi], addr + (SM_AL - SM_AH));
            }
#pragma unroll
            for (int ng = 0; ng < NG; ng++) {
                uint32_t addr = b_lm + ng * 16 * LDS_STRIDE + ks * 32;
                ldmx4(bH[ng], addr);
                ldmx4(bL[ng], addr + (SM_BL - SM_BH));
            }
#pragma unroll
            for (int mi = 0; mi < 2; mi++) {
#pragma unroll
                for (int ng = 0; ng < NG; ng++) {
#pragma unroll
                    for (int nb = 0; nb < 2; nb++) {
                        int ni = ng * 2 + nb;
                        uint32_t bh2[2] = {bH[ng][nb], bH[ng][nb + 2]};
                        uint32_t bl2[2] = {bL[ng][nb], bL[ng][nb + 2]};
                        mma_bf16(acc[mi][ni], aH[mi], bh2);
                        mma_bf16(acc[mi][ni], aH[mi], bl2);
                        mma_bf16(acc[mi][ni], aL[mi], bh2);
                    }
                }
            }
        }
    }

    // ---- epilogue ----
    const int g = lane >> 2;
    const int t4 = lane & 3;
#pragma unroll
    for (int mi = 0; mi < 2; mi++) {
#pragma unroll
        for (int ni = 0; ni < NI; ni++) {
            int col = n0 + wn * (BN / 2) + ni * 8 + t4 * 2;
            int row0 = m0 + wm * 32 + mi * 16 + g;
            int row1 = row0 + 8;
            float2 v0 = make_float2(acc[mi][ni][0], acc[mi][ni][1]);
            float2 v1 = make_float2(acc[mi][ni][2], acc[mi][ni][3]);
            if (RELU) {
                v0.x = fmaxf(v0.x, 0.f); v0.y = fmaxf(v0.y, 0.f);
                v1.x = fmaxf(v1.x, 0.f); v1.y = fmaxf(v1.y, 0.f);
            }
            if (row0 < M)
                *reinterpret_cast<float2*>(C + (size_t)row0 * N + col) = v0;
            if (row1 < M)
                *reinterpret_cast<float2*>(C + (size_t)row1 * N + col) = v1;
        }
    }
}

// ---------------------------------------------------------------------------
// log_softmax in-place over rows of 64, one warp per row (2 elems/lane)
// ---------------------------------------------------------------------------
__global__ void log_softmax_kernel(float* __restrict__ out, int M) {
    int row = blockIdx.x * (blockDim.x >> 5) + (threadIdx.x >> 5);
    int lane = threadIdx.x & 31;
    if (row >= M) return;
    float* p = out + (size_t)row * D_OUT;
    float a = p[lane];
    float b = p[lane + 32];
    float mx = fmaxf(a, b);
#pragma unroll
    for (int off = 16; off > 0; off >>= 1)
        mx = fmaxf(mx, __shfl_xor_sync(0xffffffffu, mx, off));
    float s = expf(a - mx) + expf(b - mx);
#pragma unroll
    for (int off = 16; off > 0; off >>= 1)
        s += __shfl_xor_sync(0xffffffffu, s, off);
    float l = mx + logf(s);
    p[lane] = a - l;
    p[lane + 32] = b - l;
}

// ---------------------------------------------------------------------------
// launch
// ---------------------------------------------------------------------------
extern "C" void kernel_launch(void* const* d_in, const int* in_sizes, int n_in,
                              void* d_out, int out_size) {
    const float* x = (const float*)d_in[0];
    const int* ei = (const int*)d_in[1];
    const float* W1 = (const float*)d_in[2];
    const float* W2 = (const float*)d_in[3];
    float* out = (float*)d_out;

    const int* src = ei;
    const int* dst = ei + N_EDGES;

    float *h1, *h2;
    int *deg, *off, *cursor, *adj;
    __nv_bfloat16 *w1h, *w1l, *w2h, *w2l;
    cudaGetSymbolAddress((void**)&h1, g_buf0);
    cudaGetSymbolAddress((void**)&h2, g_buf1);
    cudaGetSymbolAddress((void**)&deg, g_deg);
    cudaGetSymbolAddress((void**)&off, g_off);
    cudaGetSymbolAddress((void**)&cursor, g_cursor);
    cudaGetSymbolAddress((void**)&adj, g_adj);
    cudaGetSymbolAddress((void**)&w1h, g_w1_hi);
    cudaGetSymbolAddress((void**)&w1l, g_w1_lo);
    cudaGetSymbolAddress((void**)&w2h, g_w2_hi);
    cudaGetSymbolAddress((void**)&w2l, g_w2_lo);

    // weight split (cheap, independent)
    split_w<<<(D_IN * D_IN + 255) / 256, 256>>>(W1, w1h, w1l, D_IN * D_IN);
    split_w<<<(D_OUT * D_IN + 255) / 256, 256>>>(W2, w2h, w2l, D_OUT * D_IN);

    // CSR build (by destination)
    csr_zero_deg<<<(N_NODES + 255) / 256, 256>>>(deg);
    csr_hist<<<(N_EDGES + 255) / 256, 256>>>(dst, deg);
    csr_scan<<<1, 1024>>>(deg, off, cursor);
    csr_fill<<<(N_EDGES + 255) / 256, 256>>>(src, dst, cursor, adj);

    const int n_mtiles = (N_NODES + 127) / 128;  // 157

    // propagate 1: h1 = segment_sum(x[src] -> dst)
    gather_prop<<<N_NODES, 128>>>(x, off, adj, h1);

    // GEMM1 + ReLU: h2 = relu(h1 @ W1^T), BN=128
    {
        dim3 grid(n_mtiles, D_IN / 128);
        gemm_mma<128, true><<<grid, 256>>>(h1, w1h, w1l, h2, N_NODES, D_IN);
    }

    // propagate 2: h3(=h1) = segment_sum(h2[src] -> dst)
    gather_prop<<<N_NODES, 128>>>(h2, off, adj, h1);

    // GEMM2: out = h3 @ W2^T, BN=64
    {
        dim3 grid(n_mtiles, 1);
        gemm_mma<64, false><<<grid, 256>>>(h1, w2h, w2l, out, N_NODES, D_OUT);
    }

    // log_softmax in-place
    log_softmax_kernel<<<(N_NODES + 7) / 8, 256>>>(out, N_NODES);
}

// round 11
// speedup vs baseline: 1.5491x; 1.0759x over previous
#include <cuda_runtime.h>
#include <cuda_bf16.h>
#include <cstdint>

#define N_NODES 20000
#define D_IN 512
#define D_OUT 64
#define N_EDGES 160000

// ---------------------------------------------------------------------------
// device globals (no allocation allowed)
// ---------------------------------------------------------------------------
__device__ float g_buf0[(size_t)N_NODES * D_IN];   // h1, later z
__device__ float g_buf1[(size_t)N_NODES * D_IN];   // h2
__device__ int g_deg[N_NODES];
__device__ int g_off[N_NODES + 1];
__device__ int g_cursor[N_NODES];
__device__ int g_adj[N_EDGES];
__device__ __nv_bfloat16 g_w1_hi[D_IN * D_IN];
__device__ __nv_bfloat16 g_w1_lo[D_IN * D_IN];
__device__ __nv_bfloat16 g_w2_hi[D_OUT * D_IN];
__device__ __nv_bfloat16 g_w2_lo[D_OUT * D_IN];

// ---------------------------------------------------------------------------
// CSR build
// ---------------------------------------------------------------------------
__global__ void csr_zero_deg(int* deg) {
    int i = blockIdx.x * blockDim.x + threadIdx.x;
    if (i < N_NODES) deg[i] = 0;
}
__global__ void csr_hist(const int* __restrict__ dst, int* __restrict__ deg) {
    int e = blockIdx.x * blockDim.x + threadIdx.x;
    if (e < N_EDGES) atomicAdd(&deg[dst[e]], 1);
}
__global__ void csr_scan(const int* __restrict__ deg, int* __restrict__ off,
                         int* __restrict__ cursor) {
    __shared__ int ssum[1024];
    const int t = threadIdx.x;
    const int ITEMS = 20;
    int base = t * ITEMS;
    int local[ITEMS];
    int s = 0;
#pragma unroll
    for (int i = 0; i < ITEMS; i++) {
        int idx = base + i;
        int v = (idx < N_NODES) ? deg[idx] : 0;
        local[i] = s;
        s += v;
    }
    ssum[t] = s;
    __syncthreads();
    for (int d = 1; d < 1024; d <<= 1) {
        int v = (t >= d) ? ssum[t - d] : 0;
        __syncthreads();
        ssum[t] += v;
        __syncthreads();
    }
    int prev = (t > 0) ? ssum[t - 1] : 0;
#pragma unroll
    for (int i = 0; i < ITEMS; i++) {
        int idx = base + i;
        if (idx < N_NODES) {
            int o = prev + local[i];
            off[idx] = o;
            cursor[idx] = o;
        }
    }
    if (t == 1023) off[N_NODES] = ssum[1023];
}
__global__ void csr_fill(const int* __restrict__ src, const int* __restrict__ dst,
                         int* __restrict__ cursor, int* __restrict__ adj) {
    int e = blockIdx.x * blockDim.x + threadIdx.x;
    if (e < N_EDGES) {
        int p = atomicAdd(&cursor[dst[e]], 1);
        adj[p] = src[e];
    }
}

// ---------------------------------------------------------------------------
// Gather propagate, 512-wide (one block of 128 per node, float4 per thread)
// ---------------------------------------------------------------------------
__global__ void gather_prop(const float* __restrict__ x,
                            const int* __restrict__ off,
                            const int* __restrict__ adj,
                            float* __restrict__ out) {
    const int node = blockIdx.x;
    const int t = threadIdx.x;
    int b = off[node];
    int e = off[node + 1];
    float4 acc = make_float4(0.f, 0.f, 0.f, 0.f);
    int i = b;
    for (; i + 1 < e; i += 2) {
        int s0 = adj[i];
        int s1 = adj[i + 1];
        float4 v0 = reinterpret_cast<const float4*>(x + (size_t)s0 * D_IN)[t];
        float4 v1 = reinterpret_cast<const float4*>(x + (size_t)s1 * D_IN)[t];
        acc.x += v0.x + v1.x;
        acc.y += v0.y + v1.y;
        acc.z += v0.z + v1.z;
        acc.w += v0.w + v1.w;
    }
    if (i < e) {
        int s0 = adj[i];
        float4 v0 = reinterpret_cast<const float4*>(x + (size_t)s0 * D_IN)[t];
        acc.x += v0.x;
        acc.y += v0.y;
        acc.z += v0.z;
        acc.w += v0.w;
    }
    reinterpret_cast<float4*>(out + (size_t)node * D_IN)[t] = acc;
}

// ---------------------------------------------------------------------------
// Gather propagate 64-wide + fused log_softmax.
// One warp per node: lane owns cols {lane, lane+32}.
// out[node] = log_softmax( sum_{e: dst=node} z[src_e] )
// ---------------------------------------------------------------------------
__global__ void gather64_softmax(const float* __restrict__ z,
                                 const int* __restrict__ off,
                                 const int* __restrict__ adj,
                                 float* __restrict__ out) {
    const int node = blockIdx.x * (blockDim.x >> 5) + (threadIdx.x >> 5);
    const int lane = threadIdx.x & 31;
    if (node >= N_NODES) return;
    int b = off[node];
    int e = off[node + 1];
    float a0 = 0.f, a1 = 0.f;
    for (int i = b; i < e; i++) {
        const float* zp = z + (size_t)adj[i] * D_OUT;
        a0 += zp[lane];
        a1 += zp[lane + 32];
    }
    float mx = fmaxf(a0, a1);
#pragma unroll
    for (int o = 16; o > 0; o >>= 1)
        mx = fmaxf(mx, __shfl_xor_sync(0xffffffffu, mx, o));
    float s = expf(a0 - mx) + expf(a1 - mx);
#pragma unroll
    for (int o = 16; o > 0; o >>= 1)
        s += __shfl_xor_sync(0xffffffffu, s, o);
    float l = mx + logf(s);
    float* p = out + (size_t)node * D_OUT;
    p[lane] = a0 - l;
    p[lane + 32] = a1 - l;
}

// ---------------------------------------------------------------------------
// Split fp32 weight matrix into bf16 hi/lo
// ---------------------------------------------------------------------------
__global__ void split_w(const float* __restrict__ w, __nv_bfloat16* __restrict__ hi,
                        __nv_bfloat16* __restrict__ lo, int n) {
    int i = blockIdx.x * blockDim.x + threadIdx.x;
    if (i < n) {
        float a = w[i];
        __nv_bfloat16 h = __float2bfloat16_rn(a);
        hi[i] = h;
        lo[i] = __float2bfloat16_rn(a - __bfloat162float(h));
    }
}

// ---------------------------------------------------------------------------
// mma.sync helpers
// ---------------------------------------------------------------------------
__device__ __forceinline__ void mma_bf16(float* d, const uint32_t* a,
                                         const uint32_t* b) {
    asm volatile(
        "mma.sync.aligned.m16n8k16.row.col.f32.bf16.bf16.f32 "
        "{%0,%1,%2,%3}, {%4,%5,%6,%7}, {%8,%9}, {%0,%1,%2,%3};"
        : "+f"(d[0]), "+f"(d[1]), "+f"(d[2]), "+f"(d[3])
        : "r"(a[0]), "r"(a[1]), "r"(a[2]), "r"(a[3]), "r"(b[0]), "r"(b[1]));
}

__device__ __forceinline__ void ldmx4(uint32_t* r, uint32_t addr) {
    asm volatile(
        "ldmatrix.sync.aligned.m8n8.x4.shared.b16 {%0,%1,%2,%3}, [%4];"
        : "=r"(r[0]), "=r"(r[1]), "=r"(r[2]), "=r"(r[3])
        : "r"(addr));
}

// ---------------------------------------------------------------------------
// Split-bf16 GEMM via mma.sync: C[M,N] = A[M,512] * B[N,512]^T
// A fp32 converted to hi/lo bf16 inline; B pre-split bf16 hi/lo.
// CTA tile 128 x BN (BN=128 or 64), BK=32, 8 warps each 32 x (BN/2).
// Register-prefetch pipeline: LDG(kc+1) issues before MMA(kc).
// smem rows padded to 80B -> conflict-free ldmatrix.
// ---------------------------------------------------------------------------
#define LDS_STRIDE 80

template <int BN, bool RELU>
__global__ __launch_bounds__(256)
void gemm_mma(const float* __restrict__ A,
              const __nv_bfloat16* __restrict__ Bh,
              const __nv_bfloat16* __restrict__ Bl,
              float* __restrict__ C, int M, int N) {
    constexpr int NI = BN / 16;
    constexpr int NG = BN / 32;
    constexpr int SM_AH = 0;
    constexpr int SM_AL = 128 * LDS_STRIDE;
    constexpr int SM_BH = 2 * 128 * LDS_STRIDE;
    constexpr int SM_BL = SM_BH + BN * LDS_STRIDE;
    constexpr int SM_TOTAL = SM_BL + BN * LDS_STRIDE;
    constexpr int BPR = 256 / BN;
    constexpr int BVEC = 4 / BPR;

    __shared__ __align__(16) char smem[SM_TOTAL];
    const int tid = threadIdx.x;
    const int lane = tid & 31;
    const int wid = tid >> 5;
    const int wm = wid & 3;
    const int wn = wid >> 2;
    const int m0 = blockIdx.x * 128;
    const int n0 = blockIdx.y * BN;

    const uint32_t sb = (uint32_t)__cvta_generic_to_shared(smem);

    float acc[2][NI][4];
#pragma unroll
    for (int i = 0; i < 2; i++)
#pragma unroll
        for (int j = 0; j < NI; j++)
#pragma unroll
            for (int k = 0; k < 4; k++) acc[i][j][k] = 0.f;

    const int ar = tid >> 1;
    const int ah = tid & 1;
    const bool arow_ok = (m0 + ar) < M;
    const int br = tid / BPR;
    const int bq = tid % BPR;

    const uint32_t a_lm = sb + (uint32_t)((wm * 32 + (lane & 15)) * LDS_STRIDE +
                                          (lane >> 4) * 16);
    const uint32_t b_lm = sb + SM_BH +
        (uint32_t)((wn * (BN / 2) + (lane & 15)) * LDS_STRIDE + (lane >> 4) * 16);

    float4 av[4];
    uint4 bhv[BVEC], blv[BVEC];

    auto load_tile = [&](int kc) {
        if (arow_ok) {
            const float4* ap = reinterpret_cast<const float4*>(
                A + (size_t)(m0 + ar) * D_IN + kc * 32 + ah * 16);
#pragma unroll
            for (int i = 0; i < 4; i++) av[i] = ap[i];
        } else {
#pragma unroll
            for (int i = 0; i < 4; i++) av[i] = make_float4(0.f, 0.f, 0.f, 0.f);
        }
        const uint4* bh = reinterpret_cast<const uint4*>(
            Bh + (size_t)(n0 + br) * D_IN + kc * 32 + bq * (8 * BVEC));
        const uint4* bl = reinterpret_cast<const uint4*>(
            Bl + (size_t)(n0 + br) * D_IN + kc * 32 + bq * (8 * BVEC));
#pragma unroll
        for (int i = 0; i < BVEC; i++) {
            bhv[i] = bh[i];
            blv[i] = bl[i];
        }
    };

    load_tile(0);

    for (int kc = 0; kc < 16; kc++) {
        __syncthreads();

        {
            union { __nv_bfloat162 h2[8]; uint4 u[2]; } hi, lo;
            const float* f = reinterpret_cast<const float*>(av);
#pragma unroll
            for (int j = 0; j < 8; j++) {
                float a0 = f[2 * j], a1 = f[2 * j + 1];
                __nv_bfloat16 h0 = __float2bfloat16_rn(a0);
                __nv_bfloat16 h1 = __float2bfloat16_rn(a1);
                hi.h2[j] = __halves2bfloat162(h0, h1);
                lo.h2[j] = __halves2bfloat162(
                    __float2bfloat16_rn(a0 - __bfloat162float(h0)),
                    __float2bfloat16_rn(a1 - __bfloat162float(h1)));
            }
            char* pa = smem + ar * LDS_STRIDE + ah * 32;
            *reinterpret_cast<uint4*>(pa + SM_AH) = hi.u[0];
            *reinterpret_cast<uint4*>(pa + SM_AH + 16) = hi.u[1];
            *reinterpret_cast<uint4*>(pa + SM_AL) = lo.u[0];
            *reinterpret_cast<uint4*>(pa + SM_AL + 16) = lo.u[1];
        }
        {
            char* pb = smem + br * LDS_STRIDE + bq * (16 * BVEC);
#pragma unroll
            for (int i = 0; i < BVEC; i++) {
                *reinterpret_cast<uint4*>(pb + SM_BH + i * 16) = bhv[i];
                *reinterpret_cast<uint4*>(pb + SM_BL + i * 16) = blv[i];
            }
        }
        __syncthreads();

        if (kc + 1 < 16) load_tile(kc + 1);

#pragma unroll
        for (int ks = 0; ks < 2; ks++) {
            uint32_t aH[2][4], aL[2][4], bH[NG][4], bL[NG][4];
#pragma unroll
            for (int mi = 0; mi < 2; mi++) {
                uint32_t addr = a_lm + mi * 16 * LDS_STRIDE + ks * 32;
                ldmx4(aH[mi], addr);
                ldmx4(aL[mi], addr + (SM_AL - SM_AH));
            }
#pragma unroll
            for (int ng = 0; ng < NG; ng++) {
                uint32_t addr = b_lm + ng * 16 * LDS_STRIDE + ks * 32;
                ldmx4(bH[ng], addr);
                ldmx4(bL[ng], addr + (SM_BL - SM_BH));
            }
#pragma unroll
            for (int mi = 0; mi < 2; mi++) {
#pragma unroll
                for (int ng = 0; ng < NG; ng++) {
#pragma unroll
                    for (int nb = 0; nb < 2; nb++) {
                        int ni = ng * 2 + nb;
                        uint32_t bh2[2] = {bH[ng][nb], bH[ng][nb + 2]};
                        uint32_t bl2[2] = {bL[ng][nb], bL[ng][nb + 2]};
                        mma_bf16(acc[mi][ni], aH[mi], bh2);
                        mma_bf16(acc[mi][ni], aH[mi], bl2);
                        mma_bf16(acc[mi][ni], aL[mi], bh2);
                    }
                }
            }
        }
    }

    const int g = lane >> 2;
    const int t4 = lane & 3;
#pragma unroll
    for (int mi = 0; mi < 2; mi++) {
#pragma unroll
        for (int ni = 0; ni < NI; ni++) {
            int col = n0 + wn * (BN / 2) + ni * 8 + t4 * 2;
            int row0 = m0 + wm * 32 + mi * 16 + g;
            int row1 = row0 + 8;
            float2 v0 = make_float2(acc[mi][ni][0], acc[mi][ni][1]);
            float2 v1 = make_float2(acc[mi][ni][2], acc[mi][ni][3]);
            if (RELU) {
                v0.x = fmaxf(v0.x, 0.f); v0.y = fmaxf(v0.y, 0.f);
                v1.x = fmaxf(v1.x, 0.f); v1.y = fmaxf(v1.y, 0.f);
            }
            if (row0 < M)
                *reinterpret_cast<float2*>(C + (size_t)row0 * N + col) = v0;
            if (row1 < M)
                *reinterpret_cast<float2*>(C + (size_t)row1 * N + col) = v1;
        }
    }
}

// ---------------------------------------------------------------------------
// launch
// ---------------------------------------------------------------------------
extern "C" void kernel_launch(void* const* d_in, const int* in_sizes, int n_in,
                              void* d_out, int out_size) {
    const float* x = (const float*)d_in[0];
    const int* ei = (const int*)d_in[1];
    const float* W1 = (const float*)d_in[2];
    const float* W2 = (const float*)d_in[3];
    float* out = (float*)d_out;

    const int* src = ei;
    const int* dst = ei + N_EDGES;

    float *h1, *h2;
    int *deg, *off, *cursor, *adj;
    __nv_bfloat16 *w1h, *w1l, *w2h, *w2l;
    cudaGetSymbolAddress((void**)&h1, g_buf0);
    cudaGetSymbolAddress((void**)&h2, g_buf1);
    cudaGetSymbolAddress((void**)&deg, g_deg);
    cudaGetSymbolAddress((void**)&off, g_off);
    cudaGetSymbolAddress((void**)&cursor, g_cursor);
    cudaGetSymbolAddress((void**)&adj, g_adj);
    cudaGetSymbolAddress((void**)&w1h, g_w1_hi);
    cudaGetSymbolAddress((void**)&w1l, g_w1_lo);
    cudaGetSymbolAddress((void**)&w2h, g_w2_hi);
    cudaGetSymbolAddress((void**)&w2l, g_w2_lo);

    // weight split (cheap, independent)
    split_w<<<(D_IN * D_IN + 255) / 256, 256>>>(W1, w1h, w1l, D_IN * D_IN);
    split_w<<<(D_OUT * D_IN + 255) / 256, 256>>>(W2, w2h, w2l, D_OUT * D_IN);

    // CSR build (by destination)
    csr_zero_deg<<<(N_NODES + 255) / 256, 256>>>(deg);
    csr_hist<<<(N_EDGES + 255) / 256, 256>>>(dst, deg);
    csr_scan<<<1, 1024>>>(deg, off, cursor);
    csr_fill<<<(N_EDGES + 255) / 256, 256>>>(src, dst, cursor, adj);

    const int n_mtiles = (N_NODES + 127) / 128;  // 157

    // propagate 1: h1 = segment_sum(x[src] -> dst)   [20000, 512]
    gather_prop<<<N_NODES, 128>>>(x, off, adj, h1);

    // GEMM1 + ReLU: h2 = relu(h1 @ W1^T)             [20000, 512]
    {
        dim3 grid(n_mtiles, D_IN / 128);
        gemm_mma<128, true><<<grid, 256>>>(h1, w1h, w1l, h2, N_NODES, D_IN);
    }

    // GEMM2 FIRST (P commutes with right-mul): z = h2 @ W2^T  [20000, 64]
    // reuse buf0 (h1 is dead)
    {
        dim3 grid(n_mtiles, 1);
        gemm_mma<64, false><<<grid, 256>>>(h2, w2h, w2l, h1, N_NODES, D_OUT);
    }

    // propagate 2 (64-wide) + fused log_softmax:
    // out = log_softmax(segment_sum(z[src] -> dst))
    gather64_softmax<<<(N_NODES + 7) / 8, 256>>>(h1, off, adj, out);
}

// round 12
// speedup vs baseline: 1.9130x; 1.2350x over previous
#include <cuda_runtime.h>
#include <cuda_fp16.h>
#include <cuda_bf16.h>
#include <cstdint>

#define N_NODES 20000
#define D_IN 512
#define D_OUT 64
#define N_EDGES 160000

// ---------------------------------------------------------------------------
// device globals (no allocation allowed)
// ---------------------------------------------------------------------------
__device__ float g_buf0[(size_t)N_NODES * D_IN];   // h1, later z
__device__ float g_buf1[(size_t)N_NODES * D_IN];   // h2
__device__ int g_deg[N_NODES];
__device__ int g_off[N_NODES + 1];
__device__ int g_cursor[N_NODES];
__device__ int g_adj[N_EDGES];
__device__ __half g_w1_h[D_IN * D_IN];
__device__ __half g_w2_h[D_OUT * D_IN];

// ---------------------------------------------------------------------------
// CSR build
// ---------------------------------------------------------------------------
__global__ void csr_zero_deg(int* deg) {
    int i = blockIdx.x * blockDim.x + threadIdx.x;
    if (i < N_NODES) deg[i] = 0;
}
__global__ void csr_hist(const int* __restrict__ dst, int* __restrict__ deg) {
    int e = blockIdx.x * blockDim.x + threadIdx.x;
    if (e < N_EDGES) atomicAdd(&deg[dst[e]], 1);
}
__global__ void csr_scan(const int* __restrict__ deg, int* __restrict__ off,
                         int* __restrict__ cursor) {
    __shared__ int ssum[1024];
    const int t = threadIdx.x;
    const int ITEMS = 20;
    int base = t * ITEMS;
    int local[ITEMS];
    int s = 0;
#pragma unroll
    for (int i = 0; i < ITEMS; i++) {
        int idx = base + i;
        int v = (idx < N_NODES) ? deg[idx] : 0;
        local[i] = s;
        s += v;
    }
    ssum[t] = s;
    __syncthreads();
    for (int d = 1; d < 1024; d <<= 1) {
        int v = (t >= d) ? ssum[t - d] : 0;
        __syncthreads();
        ssum[t] += v;
        __syncthreads();
    }
    int prev = (t > 0) ? ssum[t - 1] : 0;
#pragma unroll
    for (int i = 0; i < ITEMS; i++) {
        int idx = base + i;
        if (idx < N_NODES) {
            int o = prev + local[i];
            off[idx] = o;
            cursor[idx] = o;
        }
    }
    if (t == 1023) off[N_NODES] = ssum[1023];
}
__global__ void csr_fill(const int* __restrict__ src, const int* __restrict__ dst,
                         int* __restrict__ cursor, int* __restrict__ adj) {
    int e = blockIdx.x * blockDim.x + threadIdx.x;
    if (e < N_EDGES) {
        int p = atomicAdd(&cursor[dst[e]], 1);
        adj[p] = src[e];
    }
}

// ---------------------------------------------------------------------------
// Gather propagate, 512-wide (one block of 128 per node, float4 per thread)
// ---------------------------------------------------------------------------
__global__ void gather_prop(const float* __restrict__ x,
                            const int* __restrict__ off,
                            const int* __restrict__ adj,
                            float* __restrict__ out) {
    const int node = blockIdx.x;
    const int t = threadIdx.x;
    int b = off[node];
    int e = off[node + 1];
    float4 acc = make_float4(0.f, 0.f, 0.f, 0.f);
    int i = b;
    for (; i + 1 < e; i += 2) {
        int s0 = adj[i];
        int s1 = adj[i + 1];
        float4 v0 = reinterpret_cast<const float4*>(x + (size_t)s0 * D_IN)[t];
        float4 v1 = reinterpret_cast<const float4*>(x + (size_t)s1 * D_IN)[t];
        acc.x += v0.x + v1.x;
        acc.y += v0.y + v1.y;
        acc.z += v0.z + v1.z;
        acc.w += v0.w + v1.w;
    }
    if (i < e) {
        int s0 = adj[i];
        float4 v0 = reinterpret_cast<const float4*>(x + (size_t)s0 * D_IN)[t];
        acc.x += v0.x;
        acc.y += v0.y;
        acc.z += v0.z;
        acc.w += v0.w;
    }
    reinterpret_cast<float4*>(out + (size_t)node * D_IN)[t] = acc;
}

// ---------------------------------------------------------------------------
// Gather propagate 64-wide + fused log_softmax (one warp per node)
// ---------------------------------------------------------------------------
__global__ void gather64_softmax(const float* __restrict__ z,
                                 const int* __restrict__ off,
                                 const int* __restrict__ adj,
                                 float* __restrict__ out) {
    const int node = blockIdx.x * (blockDim.x >> 5) + (threadIdx.x >> 5);
    const int lane = threadIdx.x & 31;
    if (node >= N_NODES) return;
    int b = off[node];
    int e = off[node + 1];
    float a0 = 0.f, a1 = 0.f;
    for (int i = b; i < e; i++) {
        const float* zp = z + (size_t)adj[i] * D_OUT;
        a0 += zp[lane];
        a1 += zp[lane + 32];
    }
    float mx = fmaxf(a0, a1);
#pragma unroll
    for (int o = 16; o > 0; o >>= 1)
        mx = fmaxf(mx, __shfl_xor_sync(0xffffffffu, mx, o));
    float s = expf(a0 - mx) + expf(a1 - mx);
#pragma unroll
    for (int o = 16; o > 0; o >>= 1)
        s += __shfl_xor_sync(0xffffffffu, s, o);
    float l = mx + logf(s);
    float* p = out + (size_t)node * D_OUT;
    p[lane] = a0 - l;
    p[lane + 32] = a1 - l;
}

// ---------------------------------------------------------------------------
// Round fp32 weight matrix to fp16
// ---------------------------------------------------------------------------
__global__ void round_w(const float* __restrict__ w, __half* __restrict__ h, int n) {
    int i = blockIdx.x * blockDim.x + threadIdx.x;
    if (i < n) h[i] = __float2half_rn(w[i]);
}

// ---------------------------------------------------------------------------
// mma.sync helpers (fp16 inputs, fp32 accumulate)
// ---------------------------------------------------------------------------
__device__ __forceinline__ void mma_fp16(float* d, const uint32_t* a,
                                         const uint32_t* b) {
    asm volatile(
        "mma.sync.aligned.m16n8k16.row.col.f32.f16.f16.f32 "
        "{%0,%1,%2,%3}, {%4,%5,%6,%7}, {%8,%9}, {%0,%1,%2,%3};"
        : "+f"(d[0]), "+f"(d[1]), "+f"(d[2]), "+f"(d[3])
        : "r"(a[0]), "r"(a[1]), "r"(a[2]), "r"(a[3]), "r"(b[0]), "r"(b[1]));
}

__device__ __forceinline__ void ldmx4(uint32_t* r, uint32_t addr) {
    asm volatile(
        "ldmatrix.sync.aligned.m8n8.x4.shared.b16 {%0,%1,%2,%3}, [%4];"
        : "=r"(r[0]), "=r"(r[1]), "=r"(r[2]), "=r"(r[3])
        : "r"(addr));
}

// ---------------------------------------------------------------------------
// fp16 2-term split GEMM via mma.sync: C[M,N] = A[M,512] * B[N,512]^T
// A fp32 -> fp16 hi+lo inline (A exact to ~2^-22); B pre-rounded fp16.
// C = Ah*Bh + Al*Bh; error = A*(B - Bh) ~ 2^-12 RMS.
// CTA tile 128 x BN, BK=32, 8 warps each 32 x (BN/2).
// Register-prefetch: LDG(kc+1) issued before MMA(kc).
// ---------------------------------------------------------------------------
#define LDS_STRIDE 80

template <int BN, bool RELU>
__global__ __launch_bounds__(256)
void gemm_mma(const float* __restrict__ A,
              const __half* __restrict__ Bh,
              float* __restrict__ C, int M, int N) {
    constexpr int NI = BN / 16;
    constexpr int NG = BN / 32;
    constexpr int SM_AH = 0;
    constexpr int SM_AL = 128 * LDS_STRIDE;
    constexpr int SM_BH = 2 * 128 * LDS_STRIDE;
    constexpr int SM_TOTAL = SM_BH + BN * LDS_STRIDE;
    constexpr int BPR = 256 / BN;        // threads per B row
    constexpr int BVEC = 4 / BPR;        // uint4 per thread (B tile 64B/row)

    __shared__ __align__(16) char smem[SM_TOTAL];
    const int tid = threadIdx.x;
    const int lane = tid & 31;
    const int wid = tid >> 5;
    const int wm = wid & 3;
    const int wn = wid >> 2;
    const int m0 = blockIdx.x * 128;
    const int n0 = blockIdx.y * BN;

    const uint32_t sb = (uint32_t)__cvta_generic_to_shared(smem);

    float acc[2][NI][4];
#pragma unroll
    for (int i = 0; i < 2; i++)
#pragma unroll
        for (int j = 0; j < NI; j++)
#pragma unroll
            for (int k = 0; k < 4; k++) acc[i][j][k] = 0.f;

    const int ar = tid >> 1;
    const int ah = tid & 1;
    const bool arow_ok = (m0 + ar) < M;
    const int br = tid / BPR;
    const int bq = tid % BPR;

    const uint32_t a_lm = sb + (uint32_t)((wm * 32 + (lane & 15)) * LDS_STRIDE +
                                          (lane >> 4) * 16);
    const uint32_t b_lm = sb + SM_BH +
        (uint32_t)((wn * (BN / 2) + (lane & 15)) * LDS_STRIDE + (lane >> 4) * 16);

    float4 av[4];
    uint4 bhv[BVEC];

    auto load_tile = [&](int kc) {
        if (arow_ok) {
            const float4* ap = reinterpret_cast<const float4*>(
                A + (size_t)(m0 + ar) * D_IN + kc * 32 + ah * 16);
#pragma unroll
            for (int i = 0; i < 4; i++) av[i] = ap[i];
        } else {
#pragma unroll
            for (int i = 0; i < 4; i++) av[i] = make_float4(0.f, 0.f, 0.f, 0.f);
        }
        const uint4* bh = reinterpret_cast<const uint4*>(
            Bh + (size_t)(n0 + br) * D_IN + kc * 32 + bq * (8 * BVEC));
#pragma unroll
        for (int i = 0; i < BVEC; i++) bhv[i] = bh[i];
    };

    load_tile(0);

    for (int kc = 0; kc < 16; kc++) {
        __syncthreads();

        // STS: convert A fp32 -> fp16 hi/lo
        {
            union { __half2 h2[8]; uint4 u[2]; } hi, lo;
            const float* f = reinterpret_cast<const float*>(av);
#pragma unroll
            for (int j = 0; j < 8; j++) {
                float a0 = f[2 * j], a1 = f[2 * j + 1];
                __half h0 = __float2half_rn(a0);
                __half h1 = __float2half_rn(a1);
                hi.h2[j] = __halves2half2(h0, h1);
                lo.h2[j] = __halves2half2(
                    __float2half_rn(a0 - __half2float(h0)),
                    __float2half_rn(a1 - __half2float(h1)));
            }
            char* pa = smem + ar * LDS_STRIDE + ah * 32;
            *reinterpret_cast<uint4*>(pa + SM_AH) = hi.u[0];
            *reinterpret_cast<uint4*>(pa + SM_AH + 16) = hi.u[1];
            *reinterpret_cast<uint4*>(pa + SM_AL) = lo.u[0];
            *reinterpret_cast<uint4*>(pa + SM_AL + 16) = lo.u[1];
        }
        {
            char* pb = smem + SM_BH + br * LDS_STRIDE + bq * (16 * BVEC);
#pragma unroll
            for (int i = 0; i < BVEC; i++)
                *reinterpret_cast<uint4*>(pb + i * 16) = bhv[i];
        }
        __syncthreads();

        if (kc + 1 < 16) load_tile(kc + 1);

        // compute: 2 ksteps of 16
#pragma unroll
        for (int ks = 0; ks < 2; ks++) {
            uint32_t aH[2][4], aL[2][4], bH[NG][4];
#pragma unroll
            for (int mi = 0; mi < 2; mi++) {
                uint32_t addr = a_lm + mi * 16 * LDS_STRIDE + ks * 32;
                ldmx4(aH[mi], addr);
                ldmx4(aL[mi], addr + (SM_AL - SM_AH));
            }
#pragma unroll
            for (int ng = 0; ng < NG; ng++) {
                uint32_t addr = b_lm + ng * 16 * LDS_STRIDE + ks * 32;
                ldmx4(bH[ng], addr);
            }
#pragma unroll
            for (int mi = 0; mi < 2; mi++) {
#pragma unroll
                for (int ng = 0; ng < NG; ng++) {
#pragma unroll
                    for (int nb = 0; nb < 2; nb++) {
                        int ni = ng * 2 + nb;
                        uint32_t bh2[2] = {bH[ng][nb], bH[ng][nb + 2]};
                        mma_fp16(acc[mi][ni], aH[mi], bh2);
                        mma_fp16(acc[mi][ni], aL[mi], bh2);
                    }
                }
            }
        }
    }

    // epilogue
    const int g = lane >> 2;
    const int t4 = lane & 3;
#pragma unroll
    for (int mi = 0; mi < 2; mi++) {
#pragma unroll
        for (int ni = 0; ni < NI; ni++) {
            int col = n0 + wn * (BN / 2) + ni * 8 + t4 * 2;
            int row0 = m0 + wm * 32 + mi * 16 + g;
            int row1 = row0 + 8;
            float2 v0 = make_float2(acc[mi][ni][0], acc[mi][ni][1]);
            float2 v1 = make_float2(acc[mi][ni][2], acc[mi][ni][3]);
            if (RELU) {
                v0.x = fmaxf(v0.x, 0.f); v0.y = fmaxf(v0.y, 0.f);
                v1.x = fmaxf(v1.x, 0.f); v1.y = fmaxf(v1.y, 0.f);
            }
            if (row0 < M)
                *reinterpret_cast<float2*>(C + (size_t)row0 * N + col) = v0;
            if (row1 < M)
                *reinterpret_cast<float2*>(C + (size_t)row1 * N + col) = v1;
        }
    }
}

// ---------------------------------------------------------------------------
// launch
// ---------------------------------------------------------------------------
extern "C" void kernel_launch(void* const* d_in, const int* in_sizes, int n_in,
                              void* d_out, int out_size) {
    const float* x = (const float*)d_in[0];
    const int* ei = (const int*)d_in[1];
    const float* W1 = (const float*)d_in[2];
    const float* W2 = (const float*)d_in[3];
    float* out = (float*)d_out;

    const int* src = ei;
    const int* dst = ei + N_EDGES;

    float *h1, *h2;
    int *deg, *off, *cursor, *adj;
    __half *w1h, *w2h;
    cudaGetSymbolAddress((void**)&h1, g_buf0);
    cudaGetSymbolAddress((void**)&h2, g_buf1);
    cudaGetSymbolAddress((void**)&deg, g_deg);
    cudaGetSymbolAddress((void**)&off, g_off);
    cudaGetSymbolAddress((void**)&cursor, g_cursor);
    cudaGetSymbolAddress((void**)&adj, g_adj);
    cudaGetSymbolAddress((void**)&w1h, g_w1_h);
    cudaGetSymbolAddress((void**)&w2h, g_w2_h);

    // weight rounding to fp16 (cheap, independent)
    round_w<<<(D_IN * D_IN + 255) / 256, 256>>>(W1, w1h, D_IN * D_IN);
    round_w<<<(D_OUT * D_IN + 255) / 256, 256>>>(W2, w2h, D_OUT * D_IN);

    // CSR build (by destination)
    csr_zero_deg<<<(N_NODES + 255) / 256, 256>>>(deg);
    csr_hist<<<(N_EDGES + 255) / 256, 256>>>(dst, deg);
    csr_scan<<<1, 1024>>>(deg, off, cursor);
    csr_fill<<<(N_EDGES + 255) / 256, 256>>>(src, dst, cursor, adj);

    const int n_mtiles = (N_NODES + 127) / 128;  // 157

    // propagate 1: h1 = segment_sum(x[src] -> dst)   [20000, 512]
    gather_prop<<<N_NODES, 128>>>(x, off, adj, h1);

    // GEMM1 + ReLU: h2 = relu(h1 @ W1^T)             [20000, 512]
    {
        dim3 grid(n_mtiles, D_IN / 128);
        gemm_mma<128, true><<<grid, 256>>>(h1, w1h, h2, N_NODES, D_IN);
    }

    // GEMM2 first (P commutes with right-mul): z = h2 @ W2^T  [20000, 64]
    {
        dim3 grid(n_mtiles, 1);
        gemm_mma<64, false><<<grid, 256>>>(h2, w2h, h1, N_NODES, D_OUT);
    }

    // propagate 2 (64-wide) + fused log_softmax
    gather64_softmax<<<(N_NODES + 7) / 8, 256>>>(h1, off, adj, out);
}